// round 5
// baseline (speedup 1.0000x reference)
#include <cuda_runtime.h>
#include <cstdint>

// Shapes (fixed): B=128, CIN=16, COUT=16, F=512, N=32, K=2
#define BB   128
#define CI   16
#define CO   16
#define FF   512
#define NN   32
#define NTILES ((BB * FF) / 16)   // 4096 tiles of 16 (b,f)-rows
#define GRID   304                // 2 persistent blocks / SM (152 SMs)

// ---------------- smem layout ----------------
// sW    : float2[CI*CO*NN] = 64 KB   Weff[i][c][n] = (k0,k1)
// sBias : float [CO*NN]    =  2 KB   beff[c][n]
#define SW_CNT   (CI * CO * NN)
#define SMEM_BYTES (SW_CNT * 8 + CO * NN * 4)

__device__ __forceinline__ uint64_t pack2(float lo, float hi) {
    uint64_t r;
    asm("mov.b64 %0, {%1, %2};" : "=l"(r) : "f"(lo), "f"(hi));
    return r;
}
__device__ __forceinline__ void ffma2(uint64_t& acc, uint64_t a, uint64_t b) {
    asm("fma.rn.f32x2 %0, %1, %2, %0;" : "+l"(acc) : "l"(a), "l"(b));
}

__global__ __launch_bounds__(256, 2)
void fused_kernel(const float* __restrict__ x,
                  const float* __restrict__ W1, const float* __restrict__ b1,
                  const float* __restrict__ W2, const float* __restrict__ b2,
                  float* __restrict__ out)
{
    extern __shared__ uint64_t sW[];               // [i][c][n] as packed (k0,k1)
    float* sBias = (float*)(sW + SW_CNT);          // [c][n]

    const int tid = threadIdx.x;

    // ---- prologue: fold W1*W2 -> sW, bias -> sBias (per block, ~tiny) ----
    {
        const int c  = tid >> 4;
        const int np = tid & 15;
        const int n0 = 2 * np, n1 = n0 + 1;
        float w2a[16], w2b[16];
#pragma unroll
        for (int o = 0; o < CO; ++o) {
            w2a[o] = __ldg(W2 + (n0 * CO + o) * CO + c);
            w2b[o] = __ldg(W2 + (n1 * CO + o) * CO + c);
        }
        float ba = __ldg(b2 + n0 * CO + c);
        float bb = __ldg(b2 + n1 * CO + c);
#pragma unroll
        for (int o = 0; o < CO; ++o) {
            ba = fmaf(__ldg(b1 + n0 * CO + o), w2a[o], ba);
            bb = fmaf(__ldg(b1 + n1 * CO + o), w2b[o], bb);
        }
        sBias[c * NN + n0] = ba;
        sBias[c * NN + n1] = bb;
#pragma unroll
        for (int i = 0; i < CI; ++i) {
            float s0x = 0.f, s0y = 0.f, s1x = 0.f, s1y = 0.f;
            const float2* wa = (const float2*)(W1 + ((size_t)(n0 * CI + i) * CO) * 2);
            const float2* wb = (const float2*)(W1 + ((size_t)(n1 * CI + i) * CO) * 2);
#pragma unroll
            for (int o = 0; o < CO; ++o) {
                float2 a  = __ldg(wa + o);
                float2 bq = __ldg(wb + o);
                s0x = fmaf(a.x,  w2a[o], s0x);   // n0,k0
                s0y = fmaf(a.y,  w2a[o], s0y);   // n0,k1
                s1x = fmaf(bq.x, w2b[o], s1x);   // n1,k0
                s1y = fmaf(bq.y, w2b[o], s1y);   // n1,k1
            }
            sW[(i * CO + c) * NN + n0] = pack2(s0x, s0y);
            sW[(i * CO + c) * NN + n1] = pack2(s1x, s1y);
        }
    }
    __syncthreads();

    // ---- per-warp layout ----
    const int lane = tid & 31;           // n
    const int warp = tid >> 5;
    const int q    = warp & 3;           // c-quarter
    const int g    = warp >> 2;          // row-group (0,1)
    const int c0   = q * 4;

    uint64_t bp[4];
#pragma unroll
    for (int cc = 0; cc < 4; ++cc) {
        float bv = sBias[(c0 + cc) * NN + lane];
        bp[cc] = pack2(bv, bv);
    }

    const uint64_t* wbase = sW + c0 * NN + lane;   // + i*CO*NN + cc*NN

    const int bx = blockIdx.x;

    // 4-slot ring (16 % 4 == 0 -> phase is tile-invariant).
    // Invariant entering each tile: slot0 = i=0 rows, slot1 = i=1 rows.
    float xf[4][8];
    {
        const int rowbase = bx * 16 + g * 8;
        const int b = rowbase >> 9;
        const int f = rowbase & (FF - 1);
        const float* xp = x + ((size_t)b * CI * FF + f) * NN + lane;
#pragma unroll
        for (int r = 0; r < 8; ++r) xf[0][r] = __ldg(xp + (size_t)r * NN);
#pragma unroll
        for (int r = 0; r < 8; ++r) xf[1][r] = __ldg(xp + ((size_t)FF + r) * NN);
    }

    for (int tile = bx; tile < NTILES; tile += GRID) {
        const int rowbase = tile * 16 + g * 8;
        const int b = rowbase >> 9;
        const int f = rowbase & (FF - 1);
        const float* xp = x + ((size_t)b * CI * FF + f) * NN + lane;

        // next tile (clamped; values unused on the last tile)
        const int tile2 = (tile + GRID < NTILES) ? (tile + GRID) : tile;
        const int rb2 = tile2 * 16 + g * 8;
        const float* xp2 = x + ((size_t)(rb2 >> 9) * CI * FF + (rb2 & (FF - 1))) * NN + lane;

        uint64_t acc[8][4];
#pragma unroll
        for (int cc = 0; cc < 4; ++cc)
#pragma unroll
            for (int r = 0; r < 8; ++r) acc[r][cc] = bp[cc];

#pragma unroll
        for (int i = 0; i < CI; ++i) {
            uint64_t w[4];
#pragma unroll
            for (int cc = 0; cc < 4; ++cc)
                w[cc] = wbase[(i * CO + cc) * NN];

            // distance-2 prefetch into slot (i+2)&3; at i=14,15 fetch
            // next tile's i=0,1 into slots 0,1 (consumed there as i=0,1).
            if (i < CI - 2) {
#pragma unroll
                for (int r = 0; r < 8; ++r)
                    xf[(i + 2) & 3][r] = __ldg(xp + ((size_t)(i + 2) * FF + r) * NN);
            } else {
#pragma unroll
                for (int r = 0; r < 8; ++r)
                    xf[(i + 2) & 3][r] = __ldg(xp2 + ((size_t)(i - 14) * FF + r) * NN);
            }

#pragma unroll
            for (int r = 0; r < 8; ++r) {
                const uint64_t xv = pack2(xf[i & 3][r], xf[i & 3][r]);
#pragma unroll
                for (int cc = 0; cc < 4; ++cc)
                    ffma2(acc[r][cc], xv, w[cc]);
            }
        }

        // out[b, c0+cc, f+r, 2n+k] as float2 (u64) — coalesced 256B stores
        uint64_t* op = (uint64_t*)out + (((size_t)b * CO + c0) * FF + f) * NN + lane;
#pragma unroll
        for (int cc = 0; cc < 4; ++cc)
#pragma unroll
            for (int r = 0; r < 8; ++r)
                op[((size_t)cc * FF + r) * NN] = acc[r][cc];
    }
}

// ---------------------------------------------------------------------------
extern "C" void kernel_launch(void* const* d_in, const int* in_sizes, int n_in,
                              void* d_out, int out_size)
{
    const float* x  = (const float*)d_in[0];
    const float* W1 = (const float*)d_in[1];
    const float* b1 = (const float*)d_in[2];
    const float* W2 = (const float*)d_in[3];
    const float* b2 = (const float*)d_in[4];
    float* out = (float*)d_out;

    cudaFuncSetAttribute(fused_kernel, cudaFuncAttributeMaxDynamicSharedMemorySize,
                         SMEM_BYTES);
    fused_kernel<<<GRID, 256, SMEM_BYTES>>>(x, W1, b1, W2, b2, out);
}

// round 6
// speedup vs baseline: 1.0310x; 1.0310x over previous
#include <cuda_runtime.h>
#include <cstdint>

// Shapes (fixed): B=128, CIN=16, COUT=16, F=512, N=32, K=2
#define BB   128
#define CI   16
#define CO   16
#define FF   512
#define NN   32
#define NTILES ((BB * FF) / 16)   // 4096 tiles of 16 (b,f)-rows
#define GRID   304                // 2 persistent blocks / SM (152 SMs)

// ---------------- smem ----------------
// sW    : u64[CI*CO*NN] = 64 KB   Weff[i][c][n] packed (k0,k1)
// sBP   : u64[CO*NN]    =  4 KB   beff[c][n] duplicated (bv,bv)
#define SW_CNT   (CI * CO * NN)
#define SMEM_BYTES (SW_CNT * 8 + CO * NN * 8)

__device__ __forceinline__ uint64_t pack2(float lo, float hi) {
    uint64_t r;
    asm("mov.b64 %0, {%1, %2};" : "=l"(r) : "f"(lo), "f"(hi));
    return r;
}
__device__ __forceinline__ void ffma2(uint64_t& acc, uint64_t a, uint64_t b) {
    asm("fma.rn.f32x2 %0, %1, %2, %0;" : "+l"(acc) : "l"(a), "l"(b));
}

__global__ __launch_bounds__(256, 2)
void fused_kernel(const float* __restrict__ x,
                  const float* __restrict__ W1, const float* __restrict__ b1,
                  const float* __restrict__ W2, const float* __restrict__ b2,
                  float* __restrict__ out)
{
    extern __shared__ uint64_t sW[];          // [i][c][n] packed (k0,k1)
    uint64_t* sBP = sW + SW_CNT;              // [c][n] packed (bv,bv)

    const int tid = threadIdx.x;

    // ---- prologue: fold W1*W2 -> sW, bias -> sBP (proven in R5) ----
    {
        const int c  = tid >> 4;
        const int np = tid & 15;
        const int n0 = 2 * np, n1 = n0 + 1;
        float w2a[16], w2b[16];
#pragma unroll
        for (int o = 0; o < CO; ++o) {
            w2a[o] = __ldg(W2 + (n0 * CO + o) * CO + c);
            w2b[o] = __ldg(W2 + (n1 * CO + o) * CO + c);
        }
        float ba = __ldg(b2 + n0 * CO + c);
        float bb = __ldg(b2 + n1 * CO + c);
#pragma unroll
        for (int o = 0; o < CO; ++o) {
            ba = fmaf(__ldg(b1 + n0 * CO + o), w2a[o], ba);
            bb = fmaf(__ldg(b1 + n1 * CO + o), w2b[o], bb);
        }
        sBP[c * NN + n0] = pack2(ba, ba);
        sBP[c * NN + n1] = pack2(bb, bb);
#pragma unroll
        for (int i = 0; i < CI; ++i) {
            float s0x = 0.f, s0y = 0.f, s1x = 0.f, s1y = 0.f;
            const float2* wa = (const float2*)(W1 + ((size_t)(n0 * CI + i) * CO) * 2);
            const float2* wb = (const float2*)(W1 + ((size_t)(n1 * CI + i) * CO) * 2);
#pragma unroll
            for (int o = 0; o < CO; ++o) {
                float2 a  = __ldg(wa + o);
                float2 bq = __ldg(wb + o);
                s0x = fmaf(a.x,  w2a[o], s0x);   // n0,k0
                s0y = fmaf(a.y,  w2a[o], s0y);   // n0,k1
                s1x = fmaf(bq.x, w2b[o], s1x);   // n1,k0
                s1y = fmaf(bq.y, w2b[o], s1y);   // n1,k1
            }
            sW[(i * CO + c) * NN + n0] = pack2(s0x, s0y);
            sW[(i * CO + c) * NN + n1] = pack2(s1x, s1y);
        }
    }
    __syncthreads();

    // ---- per-warp layout ----
    const int lane = tid & 31;           // n
    const int warp = tid >> 5;
    const int c0   = (warp & 3) * 4;     // 4 channels
    const int g    = warp >> 2;          // row half (rows g*8 .. g*8+7)

    const uint64_t* wbase = sW + c0 * NN + lane;   // + i*CO*NN + cc*NN
    const int bx = blockIdx.x;

    // two 16-float step buffers: buffer holds (i, i+1) x 8 rows.
    // 8 steps/tile (even) -> parity invariant: xbuf[0] = i{0,1} at tile entry.
    float xbuf[2][16];
    {
        const int rowbase = bx * 16 + g * 8;
        const float* xp0 = x + ((size_t)(rowbase >> 9) * CI * FF + (rowbase & (FF - 1))) * NN + lane;
#pragma unroll
        for (int ii = 0; ii < 2; ++ii)
#pragma unroll
            for (int r = 0; r < 8; ++r)
                xbuf[0][ii * 8 + r] = __ldg(xp0 + ((size_t)ii * FF + r) * NN);
    }

    for (int tile = bx; tile < NTILES; tile += GRID) {
        const int rowbase = tile * 16 + g * 8;
        const int b = rowbase >> 9;
        const int f = rowbase & (FF - 1);
        const float* xp = x + ((size_t)b * CI * FF + f) * NN + lane;

        // delta (in floats) to the next tile's x base; 0 on the last tile
        long dnext = 0;
        if (tile + GRID < NTILES) {
            const int rb2 = (tile + GRID) * 16 + g * 8;
            dnext = ((long)(rb2 >> 9) * CI * FF + (rb2 & (FF - 1))) * NN
                  - ((long)b * CI * FF + f) * NN;
        }

        // acc init from smem bias (keeps bias out of registers)
        uint64_t acc[8][4];
#pragma unroll
        for (int cc = 0; cc < 4; ++cc) {
            const uint64_t bv = sBP[(c0 + cc) * NN + lane];
#pragma unroll
            for (int r = 0; r < 8; ++r) acc[r][cc] = bv;
        }

#pragma unroll
        for (int s = 0; s < 8; ++s) {
            const int p = s & 1;

            // prefetch step s+1 (i = 2s+2, 2s+3); at s==7 fetch next tile's i=0,1
            {
                const float* src = (s < 7) ? (xp + (size_t)(2 * s + 2) * FF * NN)
                                           : (xp + dnext);
#pragma unroll
                for (int ii = 0; ii < 2; ++ii)
#pragma unroll
                    for (int r = 0; r < 8; ++r)
                        xbuf[p ^ 1][ii * 8 + r] = __ldg(src + ((size_t)ii * FF + r) * NN);
            }

            // compute i = 2s, 2s+1 from buffer p
#pragma unroll
            for (int ii = 0; ii < 2; ++ii) {
                const int i = 2 * s + ii;
                uint64_t w[4];
#pragma unroll
                for (int cc = 0; cc < 4; ++cc)
                    w[cc] = wbase[(i * CO + cc) * NN];
#pragma unroll
                for (int r = 0; r < 8; ++r) {
                    const float xs = xbuf[p][ii * 8 + r];
                    const uint64_t xv = pack2(xs, xs);
#pragma unroll
                    for (int cc = 0; cc < 4; ++cc)
                        ffma2(acc[r][cc], xv, w[cc]);
                }
            }
        }

        // out[b, c0+cc, f+r, 2n+k] as u64 — coalesced 256B stores
        uint64_t* op = (uint64_t*)out + (((size_t)b * CO + c0) * FF + f) * NN + lane;
#pragma unroll
        for (int cc = 0; cc < 4; ++cc)
#pragma unroll
            for (int r = 0; r < 8; ++r)
                op[((size_t)cc * FF + r) * NN] = acc[r][cc];
    }
}

// ---------------------------------------------------------------------------
extern "C" void kernel_launch(void* const* d_in, const int* in_sizes, int n_in,
                              void* d_out, int out_size)
{
    const float* x  = (const float*)d_in[0];
    const float* W1 = (const float*)d_in[1];
    const float* b1 = (const float*)d_in[2];
    const float* W2 = (const float*)d_in[3];
    const float* b2 = (const float*)d_in[4];
    float* out = (float*)d_out;

    cudaFuncSetAttribute(fused_kernel, cudaFuncAttributeMaxDynamicSharedMemorySize,
                         SMEM_BYTES);
    fused_kernel<<<GRID, 256, SMEM_BYTES>>>(x, W1, b1, W2, b2, out);
}

// round 7
// speedup vs baseline: 1.0355x; 1.0044x over previous
#include <cuda_runtime.h>
#include <cstdint>

// Shapes (fixed): B=128, CIN=16, COUT=16, F=512, N=32, K=2
#define BB   128
#define CI   16
#define CO   16
#define FF   512
#define NN   32
#define NTILES ((BB * FF) / 16)   // 4096 tiles of 16 (b,f)-rows
#define GRID   304                // 2 persistent blocks / SM (152 SMs)

// ---------------- smem ----------------
// sW    : u64[CI*CO*NN] = 64 KB   Weff[i][c][n] packed (k0,k1)
// sBias : float[CO*NN]  =  2 KB   beff[c][n]
#define SW_CNT   (CI * CO * NN)
#define SMEM_BYTES (SW_CNT * 8 + CO * NN * 4)

__device__ __forceinline__ uint64_t pack2(float lo, float hi) {
    uint64_t r;
    asm("mov.b64 %0, {%1, %2};" : "=l"(r) : "f"(lo), "f"(hi));
    return r;
}
__device__ __forceinline__ void ffma2(uint64_t& acc, uint64_t a, uint64_t b) {
    asm("fma.rn.f32x2 %0, %1, %2, %0;" : "+l"(acc) : "l"(a), "l"(b));
}

// ---------------------------------------------------------------------------
// Weight fold, kept OUT of the main kernel's register allocation scope via
// noinline (the inlined version pushed ptxas past 128 regs -> spills, R5/R6).
// ---------------------------------------------------------------------------
__device__ __noinline__ void build_weights(uint64_t* sW, float* sBias,
                                           const float* W1, const float* b1,
                                           const float* W2, const float* b2,
                                           int tid)
{
    const int c  = tid >> 4;
    const int np = tid & 15;
    const int n0 = 2 * np, n1 = n0 + 1;
    float w2a[16], w2b[16];
#pragma unroll
    for (int o = 0; o < CO; ++o) {
        w2a[o] = __ldg(W2 + (n0 * CO + o) * CO + c);
        w2b[o] = __ldg(W2 + (n1 * CO + o) * CO + c);
    }
    float ba = __ldg(b2 + n0 * CO + c);
    float bb = __ldg(b2 + n1 * CO + c);
#pragma unroll
    for (int o = 0; o < CO; ++o) {
        ba = fmaf(__ldg(b1 + n0 * CO + o), w2a[o], ba);
        bb = fmaf(__ldg(b1 + n1 * CO + o), w2b[o], bb);
    }
    sBias[c * NN + n0] = ba;
    sBias[c * NN + n1] = bb;
#pragma unroll
    for (int i = 0; i < CI; ++i) {
        float s0x = 0.f, s0y = 0.f, s1x = 0.f, s1y = 0.f;
        const float2* wa = (const float2*)(W1 + ((size_t)(n0 * CI + i) * CO) * 2);
        const float2* wb = (const float2*)(W1 + ((size_t)(n1 * CI + i) * CO) * 2);
#pragma unroll
        for (int o = 0; o < CO; ++o) {
            float2 a  = __ldg(wa + o);
            float2 bq = __ldg(wb + o);
            s0x = fmaf(a.x,  w2a[o], s0x);   // n0,k0
            s0y = fmaf(a.y,  w2a[o], s0y);   // n0,k1
            s1x = fmaf(bq.x, w2b[o], s1x);   // n1,k0
            s1y = fmaf(bq.y, w2b[o], s1y);   // n1,k1
        }
        sW[(i * CO + c) * NN + n0] = pack2(s0x, s0y);
        sW[(i * CO + c) * NN + n1] = pack2(s1x, s1y);
    }
}

// ---------------------------------------------------------------------------
// Main kernel: R2's proven 84us body (124 regs, no spill) + cross-tile
// prefetch via dnext (+2 regs) + fused noinline weight fold (single launch).
// ---------------------------------------------------------------------------
__global__ __launch_bounds__(256, 2)
void fused_kernel(const float* __restrict__ x,
                  const float* __restrict__ W1, const float* __restrict__ b1,
                  const float* __restrict__ W2, const float* __restrict__ b2,
                  float* __restrict__ out)
{
    extern __shared__ uint64_t sW[];          // [i][c][n] packed (k0,k1)
    float* sBias = (float*)(sW + SW_CNT);     // [c][n]

    build_weights(sW, sBias, W1, b1, W2, b2, threadIdx.x);
    __syncthreads();

    const int tid  = threadIdx.x;
    const int lane = tid & 31;           // n
    const int warp = tid >> 5;
    const int q    = warp & 3;           // c-quarter
    const int g    = warp >> 2;          // row-group (0,1)
    const int c0   = q * 4;

    uint64_t bp[4];
#pragma unroll
    for (int cc = 0; cc < 4; ++cc) {
        float bv = sBias[(c0 + cc) * NN + lane];
        bp[cc] = pack2(bv, bv);
    }

    const uint64_t* wbase = sW + c0 * NN + lane;   // + i*CO*NN + cc*NN
    const int bx = blockIdx.x;

    // double buffer; 16 i-steps/tile (even) -> slot parity tile-invariant:
    // slot 0 holds i=0 at every tile entry.
    uint64_t xv[2][8];
    {
        const int rowbase = bx * 16 + g * 8;
        const float* xp0 = x + ((size_t)(rowbase >> 9) * CI * FF + (rowbase & (FF - 1))) * NN + lane;
#pragma unroll
        for (int r = 0; r < 8; ++r) {
            float v = __ldg(xp0 + (size_t)r * NN);
            xv[0][r] = pack2(v, v);
        }
    }

    for (int tile = bx; tile < NTILES; tile += GRID) {
        const int rowbase = tile * 16 + g * 8;
        const int b = rowbase >> 9;
        const int f = rowbase & (FF - 1);
        const float* xp = x + ((size_t)b * CI * FF + f) * NN + lane;

        // delta (in floats) to next tile's x base; 0 on last tile (safe, unused)
        long dnext = 0;
        if (tile + GRID < NTILES) {
            const int rb2 = (tile + GRID) * 16 + g * 8;
            dnext = ((long)(rb2 >> 9) * CI * FF + (rb2 & (FF - 1))) * NN
                  - ((long)b * CI * FF + f) * NN;
        }

        uint64_t acc[8][4];
#pragma unroll
        for (int cc = 0; cc < 4; ++cc)
#pragma unroll
            for (int r = 0; r < 8; ++r) acc[r][cc] = bp[cc];

#pragma unroll
        for (int i = 0; i < CI; ++i) {
            uint64_t w[4];
#pragma unroll
            for (int cc = 0; cc < 4; ++cc)
                w[cc] = wbase[(i * CO + cc) * NN];

            // prefetch i+1 into slot (i+1)&1; at i=15 fetch next tile's i=0
            // into slot 0 (consumed there as i=0).
            {
                const float* src = (i < CI - 1)
                                 ? (xp + (size_t)(i + 1) * FF * NN)
                                 : (xp + dnext);
#pragma unroll
                for (int r = 0; r < 8; ++r) {
                    float v = __ldg(src + (size_t)r * NN);
                    xv[(i + 1) & 1][r] = pack2(v, v);
                }
            }

#pragma unroll
            for (int cc = 0; cc < 4; ++cc)
#pragma unroll
                for (int r = 0; r < 8; ++r)
                    ffma2(acc[r][cc], xv[i & 1][r], w[cc]);
        }

        // out[b, c0+cc, f+r, 2n+k] as u64 — coalesced 256B stores
        uint64_t* op = (uint64_t*)out + (((size_t)b * CO + c0) * FF + f) * NN + lane;
#pragma unroll
        for (int cc = 0; cc < 4; ++cc)
#pragma unroll
            for (int r = 0; r < 8; ++r)
                op[((size_t)cc * FF + r) * NN] = acc[r][cc];
    }
}

// ---------------------------------------------------------------------------
extern "C" void kernel_launch(void* const* d_in, const int* in_sizes, int n_in,
                              void* d_out, int out_size)
{
    const float* x  = (const float*)d_in[0];
    const float* W1 = (const float*)d_in[1];
    const float* b1 = (const float*)d_in[2];
    const float* W2 = (const float*)d_in[3];
    const float* b2 = (const float*)d_in[4];
    float* out = (float*)d_out;

    cudaFuncSetAttribute(fused_kernel, cudaFuncAttributeMaxDynamicSharedMemorySize,
                         SMEM_BYTES);
    fused_kernel<<<GRID, 256, SMEM_BYTES>>>(x, W1, b1, W2, b2, out);
}

// round 8
// speedup vs baseline: 2.2482x; 2.1711x over previous
#include <cuda_runtime.h>
#include <cstdint>

// Shapes (fixed): B=128, CIN=16, COUT=16, F=512, N=32, K=2
#define BB   128
#define CI   16
#define CO   16
#define FF   512
#define NN   32
#define NTILES ((BB * FF) / 16)   // 4096 tiles of 16 (b,f)-rows
#define GRID   304                // 2 persistent blocks / SM

// Effective weights: Weff[n,i,c,k] = sum_o W1[n,i,o,k]*W2[n,o,c]
// g_W layout [i][c][n] packed (k0,k1);  g_BP[c][n] packed (bv,bv)
__device__ uint64_t g_W[CI * CO * NN];
__device__ uint64_t g_BP[CO * NN];

__device__ __forceinline__ uint64_t pack2(float lo, float hi) {
    uint64_t r;
    asm("mov.b64 %0, {%1, %2};" : "=l"(r) : "f"(lo), "f"(hi));
    return r;
}
__device__ __forceinline__ void ffma2(uint64_t& acc, uint64_t a, uint64_t b) {
    asm("fma.rn.f32x2 %0, %1, %2, %0;" : "+l"(acc) : "l"(a), "l"(b));
}

// ---------------------------------------------------------------------------
// Prologue kernel: parallel over (i, c, npair) = 512 blocks x 256 thr / 16.
// ---------------------------------------------------------------------------
__global__ void prep_kernel(const float* __restrict__ W1, const float* __restrict__ b1,
                            const float* __restrict__ W2, const float* __restrict__ b2)
{
    const int t = blockIdx.x * blockDim.x + threadIdx.x;   // 0 .. 131071 (512*256)
    // Weff: one thread per (i, c, n): 8192 threads needed
    if (t < CI * CO * NN) {
        const int n = t & 31;
        const int c = (t >> 5) & 15;
        const int i = t >> 9;
        float s0 = 0.f, s1 = 0.f;
        const float2* w1 = (const float2*)(W1 + ((size_t)(n * CI + i) * CO) * 2);
        const float*  w2 = W2 + (size_t)n * CO * CO + c;
#pragma unroll
        for (int o = 0; o < CO; ++o) {
            float2 a = __ldg(w1 + o);
            float  wv = __ldg(w2 + o * CO);
            s0 = fmaf(a.x, wv, s0);
            s1 = fmaf(a.y, wv, s1);
        }
        g_W[(i * CO + c) * NN + n] = pack2(s0, s1);
    }
    if (t < CO * NN) {
        const int n = t & 31;
        const int c = t >> 5;
        float s = __ldg(b2 + n * CO + c);
#pragma unroll
        for (int o = 0; o < CO; ++o)
            s = fmaf(__ldg(b1 + n * CO + o), __ldg(W2 + (size_t)(n * CO + o) * CO + c), s);
        g_BP[c * NN + n] = pack2(s, s);
    }
}

// ---------------------------------------------------------------------------
// Main kernel: R2 body + 4-slot raw-float x ring (distance-3 prefetch) +
// phase-safe cross-tile prefetch (16 % 4 == 0) + bias from smem.
// ---------------------------------------------------------------------------
__global__ __launch_bounds__(256, 2)
void up_kernel(const float* __restrict__ x, float* __restrict__ out)
{
    extern __shared__ uint64_t sW[];          // [i][c][n] packed (k0,k1) : 64 KB
    uint64_t* sBP = sW + CI * CO * NN;        // [c][n] packed (bv,bv)    :  4 KB

    const int tid = threadIdx.x;
    {
        const uint4* gw = (const uint4*)g_W;
        uint4* sw4 = (uint4*)sW;
#pragma unroll
        for (int idx = tid; idx < CI * CO * NN / 2; idx += 256)
            sw4[idx] = gw[idx];
        for (int idx = tid; idx < CO * NN; idx += 256)
            sBP[idx] = g_BP[idx];
    }
    __syncthreads();

    const int lane = tid & 31;           // n
    const int warp = tid >> 5;
    const int c0   = (warp & 3) * 4;     // 4 channels per warp
    const int g    = warp >> 2;          // row half

    const uint64_t* wbase = sW + c0 * NN + lane;
    const int bx = blockIdx.x;

    // 32-bit element offsets (x is 33.5M floats < 2^31)
    // tile -> x offset of row 0: ((rowbase>>9)*CI*FF + (rowbase & 511))*NN + lane
    uint32_t xoff;
    {
        const uint32_t rb = (uint32_t)bx * 16 + g * 8;
        xoff = ((rb >> 9) * (CI * FF) + (rb & (FF - 1))) * NN + lane;
    }

    // 4-slot ring of raw floats; preload slots 0..2 for the first tile
    float xf[4][8];
#pragma unroll
    for (int ii = 0; ii < 3; ++ii)
#pragma unroll
        for (int r = 0; r < 8; ++r)
            xf[ii][r] = __ldg(x + xoff + ii * (FF * NN) + r * NN);

    for (int tile = bx; tile < NTILES; tile += GRID) {
        // next tile's x offset (clamped to last tile; loads in-bounds, unused)
        const int tn = (tile + GRID < NTILES) ? (tile + GRID) : tile;
        const uint32_t rbn = (uint32_t)tn * 16 + g * 8;
        const uint32_t xoffn = ((rbn >> 9) * (CI * FF) + (rbn & (FF - 1))) * NN + lane;

        uint64_t acc[8][4];
#pragma unroll
        for (int cc = 0; cc < 4; ++cc) {
            const uint64_t bv = sBP[(c0 + cc) * NN + lane];
#pragma unroll
            for (int r = 0; r < 8; ++r) acc[r][cc] = bv;
        }

#pragma unroll
        for (int i = 0; i < CI; ++i) {
            uint64_t w[4];
#pragma unroll
            for (int cc = 0; cc < 4; ++cc)
                w[cc] = wbase[(i * CO + cc) * NN];

            // prefetch i+3 into slot (i+3)&3; for i>=13 fetch next tile's
            // rows 0..2 into slots 0..2 (phase-safe: 16 % 4 == 0).
            {
                const uint32_t po = (i < CI - 3)
                                  ? (xoff  + (uint32_t)(i + 3) * (FF * NN))
                                  : (xoffn + (uint32_t)(i - 13) * (FF * NN));
#pragma unroll
                for (int r = 0; r < 8; ++r)
                    xf[(i + 3) & 3][r] = __ldg(x + po + r * NN);
            }

#pragma unroll
            for (int r = 0; r < 8; ++r) {
                const float xs = xf[i & 3][r];
                const uint64_t xv = pack2(xs, xs);
#pragma unroll
                for (int cc = 0; cc < 4; ++cc)
                    ffma2(acc[r][cc], xv, w[cc]);
            }
        }

        // out[b, c0+cc, f+r, 2n+k] as u64 — coalesced 256B stores
        const uint32_t rb = (uint32_t)tile * 16 + g * 8;
        uint64_t* op = (uint64_t*)out
                     + ((size_t)((rb >> 9) * CO + c0) * FF + (rb & (FF - 1))) * NN + lane;
#pragma unroll
        for (int cc = 0; cc < 4; ++cc)
#pragma unroll
            for (int r = 0; r < 8; ++r)
                op[((size_t)cc * FF + r) * NN] = acc[r][cc];

        xoff = xoffn;
    }
}

// ---------------------------------------------------------------------------
extern "C" void kernel_launch(void* const* d_in, const int* in_sizes, int n_in,
                              void* d_out, int out_size)
{
    const float* x  = (const float*)d_in[0];
    const float* W1 = (const float*)d_in[1];
    const float* b1 = (const float*)d_in[2];
    const float* W2 = (const float*)d_in[3];
    const float* b2 = (const float*)d_in[4];
    float* out = (float*)d_out;

    prep_kernel<<<32, 256>>>(W1, b1, W2, b2);

    const int smem_bytes = CI * CO * NN * 8 + CO * NN * 8;   // 64 KB + 4 KB
    cudaFuncSetAttribute(up_kernel, cudaFuncAttributeMaxDynamicSharedMemorySize,
                         smem_bytes);
    up_kernel<<<GRID, 256, smem_bytes>>>(x, out);
}

// round 9
// speedup vs baseline: 2.2691x; 1.0093x over previous
#include <cuda_runtime.h>
#include <cstdint>

// Shapes (fixed): B=128, CIN=16, COUT=16, F=512, N=32, K=2
#define BB   128
#define CI   16
#define CO   16
#define FF   512
#define NN   32
#define TROWS  8                      // rows per tile (8 warps: 2 rowgroups x 4 cq)
#define NTILES ((BB * FF) / TROWS)    // 8192 tiles
#define GRID   456                    // 3 persistent blocks / SM (152 SMs)

// g_W layout [i][c][n] packed (k0,k1);  g_BP[c][n] packed (bv,bv)
__device__ uint64_t g_W[CI * CO * NN];
__device__ uint64_t g_BP[CO * NN];

__device__ __forceinline__ uint64_t pack2(float lo, float hi) {
    uint64_t r;
    asm("mov.b64 %0, {%1, %2};" : "=l"(r) : "f"(lo), "f"(hi));
    return r;
}
__device__ __forceinline__ void ffma2(uint64_t& acc, uint64_t a, uint64_t b) {
    asm("fma.rn.f32x2 %0, %1, %2, %0;" : "+l"(acc) : "l"(a), "l"(b));
}

// ---------------------------------------------------------------------------
// Prologue kernel (proven): Weff[n,i,c,k] = sum_o W1[n,i,o,k]*W2[n,o,c]
// ---------------------------------------------------------------------------
__global__ void prep_kernel(const float* __restrict__ W1, const float* __restrict__ b1,
                            const float* __restrict__ W2, const float* __restrict__ b2)
{
    const int t = blockIdx.x * blockDim.x + threadIdx.x;
    if (t < CI * CO * NN) {
        const int n = t & 31;
        const int c = (t >> 5) & 15;
        const int i = t >> 9;
        float s0 = 0.f, s1 = 0.f;
        const float2* w1 = (const float2*)(W1 + ((size_t)(n * CI + i) * CO) * 2);
        const float*  w2 = W2 + (size_t)n * CO * CO + c;
#pragma unroll
        for (int o = 0; o < CO; ++o) {
            float2 a = __ldg(w1 + o);
            float  wv = __ldg(w2 + o * CO);
            s0 = fmaf(a.x, wv, s0);
            s1 = fmaf(a.y, wv, s1);
        }
        g_W[(i * CO + c) * NN + n] = pack2(s0, s1);
    }
    if (t < CO * NN) {
        const int n = t & 31;
        const int c = t >> 5;
        float s = __ldg(b2 + n * CO + c);
#pragma unroll
        for (int o = 0; o < CO; ++o)
            s = fmaf(__ldg(b1 + n * CO + o), __ldg(W2 + (size_t)(n * CO + o) * CO + c), s);
        g_BP[c * NN + n] = pack2(s, s);
    }
}

// ---------------------------------------------------------------------------
// Main kernel: small warp tile (4 rows x 4 ch) for 3 blocks/SM = 24 warps/SM.
// ---------------------------------------------------------------------------
__global__ __launch_bounds__(256, 3)
void up_kernel(const float* __restrict__ x, float* __restrict__ out)
{
    extern __shared__ uint64_t sW[];          // [i][c][n] packed (k0,k1) : 64 KB
    uint64_t* sBP = sW + CI * CO * NN;        // [c][n] packed (bv,bv)    :  4 KB

    const int tid = threadIdx.x;
    {
        const uint4* gw = (const uint4*)g_W;
        uint4* sw4 = (uint4*)sW;
#pragma unroll
        for (int idx = tid; idx < CI * CO * NN / 2; idx += 256)
            sw4[idx] = gw[idx];
        for (int idx = tid; idx < CO * NN; idx += 256)
            sBP[idx] = g_BP[idx];
    }
    __syncthreads();

    const int lane = tid & 31;           // n
    const int warp = tid >> 5;
    const int c0   = (warp & 3) * 4;     // 4 channels per warp
    const int g    = warp >> 2;          // row group (0,1): rows g*4 .. g*4+3

    const uint64_t* wbase = sW + c0 * NN + lane;
    const int bx = blockIdx.x;

    // 32-bit element offsets (x has 33.5M floats < 2^31)
    uint32_t xoff;
    {
        const uint32_t rb = (uint32_t)bx * TROWS + g * 4;
        xoff = ((rb >> 9) * (CI * FF) + (rb & (FF - 1))) * NN + lane;
    }

    // double buffer of raw floats; 16 i-steps (even) -> parity tile-invariant
    float xf[2][4];
#pragma unroll
    for (int r = 0; r < 4; ++r)
        xf[0][r] = __ldg(x + xoff + r * NN);

    for (int tile = bx; tile < NTILES; tile += GRID) {
        // next tile's x offset (clamped; loads stay in-bounds, values unused)
        const int tn = (tile + GRID < NTILES) ? (tile + GRID) : tile;
        const uint32_t rbn = (uint32_t)tn * TROWS + g * 4;
        const uint32_t xoffn = ((rbn >> 9) * (CI * FF) + (rbn & (FF - 1))) * NN + lane;

        uint64_t acc[4][4];
#pragma unroll
        for (int cc = 0; cc < 4; ++cc) {
            const uint64_t bv = sBP[(c0 + cc) * NN + lane];
#pragma unroll
            for (int r = 0; r < 4; ++r) acc[r][cc] = bv;
        }

#pragma unroll
        for (int i = 0; i < CI; ++i) {
            uint64_t w[4];
#pragma unroll
            for (int cc = 0; cc < 4; ++cc)
                w[cc] = wbase[(i * CO + cc) * NN];

            // prefetch i+1 into slot (i+1)&1; at i=15 fetch next tile's i=0
            {
                const uint32_t po = (i < CI - 1)
                                  ? (xoff + (uint32_t)(i + 1) * (FF * NN))
                                  : xoffn;
#pragma unroll
                for (int r = 0; r < 4; ++r)
                    xf[(i + 1) & 1][r] = __ldg(x + po + r * NN);
            }

#pragma unroll
            for (int r = 0; r < 4; ++r) {
                const float xs = xf[i & 1][r];
                const uint64_t xv = pack2(xs, xs);
#pragma unroll
                for (int cc = 0; cc < 4; ++cc)
                    ffma2(acc[r][cc], xv, w[cc]);
            }
        }

        // out[b, c0+cc, f+r, 2n+k] as u64 — coalesced 256B stores
        const uint32_t rb = (uint32_t)tile * TROWS + g * 4;
        uint64_t* op = (uint64_t*)out
                     + ((size_t)((rb >> 9) * CO + c0) * FF + (rb & (FF - 1))) * NN + lane;
#pragma unroll
        for (int cc = 0; cc < 4; ++cc)
#pragma unroll
            for (int r = 0; r < 4; ++r)
                op[((size_t)cc * FF + r) * NN] = acc[r][cc];

        xoff = xoffn;
    }
}

// ---------------------------------------------------------------------------
extern "C" void kernel_launch(void* const* d_in, const int* in_sizes, int n_in,
                              void* d_out, int out_size)
{
    const float* x  = (const float*)d_in[0];
    const float* W1 = (const float*)d_in[1];
    const float* b1 = (const float*)d_in[2];
    const float* W2 = (const float*)d_in[3];
    const float* b2 = (const float*)d_in[4];
    float* out = (float*)d_out;

    prep_kernel<<<32, 256>>>(W1, b1, W2, b2);

    const int smem_bytes = CI * CO * NN * 8 + CO * NN * 8;   // 64 KB + 4 KB
    cudaFuncSetAttribute(up_kernel, cudaFuncAttributeMaxDynamicSharedMemorySize,
                         smem_bytes);
    up_kernel<<<GRID, 256, smem_bytes>>>(x, out);
}